// round 13
// baseline (speedup 1.0000x reference)
#include <cuda_runtime.h>

#define NN 50000
#define NE 800000
#define F1 128
#define F2 64
#define SCAN_T 1024
#define CHUNK ((NN + SCAN_T - 1) / SCAN_T)   // 49

typedef unsigned long long u64t;

// ---------------- packed f32x2 helpers ----------------
__device__ __forceinline__ u64t pack2(float a, float b) {
    u64t r; asm("mov.b64 %0,{%1,%2};" : "=l"(r) : "f"(a), "f"(b)); return r;
}
__device__ __forceinline__ float2 unpack2(u64t v) {
    float2 r; asm("mov.b64 {%0,%1},%2;" : "=f"(r.x), "=f"(r.y) : "l"(v)); return r;
}
__device__ __forceinline__ void ffma2(u64t& d, u64t a, u64t b) {
    asm("fma.rn.f32x2 %0,%1,%2,%0;" : "+l"(d) : "l"(a), "l"(b));
}
__device__ __forceinline__ void fadd2(u64t& d, u64t a) {
    asm("add.rn.f32x2 %0,%0,%1;" : "+l"(d) : "l"(a));
}

// ---------------- scratch (static device globals; zero-initialized at load) ----------------
__device__ int   g_degout[NN];   // re-zeroed by k_layer2 tail each run
__device__ int   g_degin[NN];    // re-zeroed by k_layer2 tail each run
__device__ float g_sout[NN];
__device__ float g_sin[NN];
__device__ int   g_rowstart[NN + 1];
__device__ int   g_cursor[NN];
__device__ int   g_csrc[NE];
__device__ float g_h2[NN * F2];

// ---------------- degree (vectorized; arrays pre-zeroed) ----------------
__global__ void k_deg(const int4* __restrict__ src4, const int4* __restrict__ dst4) {
    int i = blockIdx.x * blockDim.x + threadIdx.x;
    if (i < NE / 4) {
        int4 s = src4[i], d = dst4[i];
        atomicAdd(&g_degout[s.x], 1); atomicAdd(&g_degout[s.y], 1);
        atomicAdd(&g_degout[s.z], 1); atomicAdd(&g_degout[s.w], 1);
        atomicAdd(&g_degin[d.x], 1);  atomicAdd(&g_degin[d.y], 1);
        atomicAdd(&g_degin[d.z], 1);  atomicAdd(&g_degin[d.w], 1);
    }
}

// ---------------- single-block scan + scales + cursor init ----------------
__global__ __launch_bounds__(SCAN_T)
void k_scan_all() {
    __shared__ int wsum[32];
    int t = threadIdx.x;
    int lane = t & 31, w = t >> 5;
    int lo = t * CHUNK, hi = min(lo + CHUNK, NN);

    int sum = 0;
    for (int i = lo; i < hi; i++) sum += g_degin[i];

    int v = sum;
    #pragma unroll
    for (int off = 1; off < 32; off <<= 1) {
        int x = __shfl_up_sync(0xffffffffu, v, off);
        if (lane >= off) v += x;
    }
    if (lane == 31) wsum[w] = v;
    __syncthreads();
    if (w == 0) {
        int s = wsum[lane];
        #pragma unroll
        for (int off = 1; off < 32; off <<= 1) {
            int x = __shfl_up_sync(0xffffffffu, s, off);
            if (lane >= off) s += x;
        }
        wsum[lane] = s;
    }
    __syncthreads();

    int base = (v - sum) + ((w > 0) ? wsum[w - 1] : 0);

    for (int i = lo; i < hi; i++) {
        int din = g_degin[i];
        g_rowstart[i] = base; base += din;
        g_cursor[i] = 0;
        g_sin[i]  = rsqrtf(fmaxf((float)din, 1.0f));
        g_sout[i] = rsqrtf(fmaxf((float)g_degout[i], 1.0f));
    }
    if (t == SCAN_T - 1) g_rowstart[NN] = base;
}

__global__ void k_fill(const int4* __restrict__ src4, const int4* __restrict__ dst4) {
    int i = blockIdx.x * blockDim.x + threadIdx.x;
    if (i < NE / 4) {
        int4 s = src4[i], d = dst4[i];
        int p;
        p = atomicAdd(&g_cursor[d.x], 1); g_csrc[g_rowstart[d.x] + p] = s.x;
        p = atomicAdd(&g_cursor[d.y], 1); g_csrc[g_rowstart[d.y] + p] = s.y;
        p = atomicAdd(&g_cursor[d.z], 1); g_csrc[g_rowstart[d.z] + p] = s.z;
        p = atomicAdd(&g_cursor[d.w], 1); g_csrc[g_rowstart[d.w] + p] = s.w;
    }
}

// ---------------- fused: gather1 + GEMM1 + relu + GEMM2 ----------------
#define RPB 64  // 8 warps * 4 rows * 2 passes

__global__ __launch_bounds__(256, 2)
void k_fused(const float* __restrict__ featp, const float4* __restrict__ W1g,
             const float4* __restrict__ W2g, const float* __restrict__ b1g) {
    extern __shared__ float sm[];
    float* sW1 = sm;                       // 16384 floats
    float* sW2 = sm + F1 * F1;             // 8192 floats
    float* sBuf = sW2 + F1 * F2;           // 8 warps * 512 floats

    int tid = threadIdx.x;
    #pragma unroll 4
    for (int i = tid; i < (F1 * F1) / 4; i += 256) ((float4*)sW1)[i] = W1g[i];
    #pragma unroll 2
    for (int i = tid; i < (F1 * F2) / 4; i += 256) ((float4*)sW2)[i] = W2g[i];
    __syncthreads();

    int w = tid >> 5, lane = tid & 31;
    float* myBuf = sBuf + w * 512;
    float4 b1v = ((const float4*)b1g)[lane];
    const longlong2* feat2 = (const longlong2*)featp;
    const longlong2* sW1ll = (const longlong2*)sW1;
    const u64t*      sW2ll = (const u64t*)sW2;

    for (int pass = 0; pass < 2; pass++) {
        int r0 = blockIdx.x * RPB + pass * 32 + w * 4;

        // ---- gather 4 rows from feat via CSR (8-deep MLP batches) ----
        #pragma unroll
        for (int i = 0; i < 4; i++) {
            int r = r0 + i;
            u64t acc0 = 0, acc1 = 0;
            if (r < NN) {
                int beg = __ldg(&g_rowstart[r]), end = __ldg(&g_rowstart[r + 1]);
                for (int j = beg; j < end; j += 32) {
                    int n = min(32, end - j);
                    int sid = 0; float sv = 0.f;
                    if (lane < n) { sid = g_csrc[j + lane]; sv = g_sout[sid]; }
                    int kk = 0;
                    for (; kk + 8 <= n; kk += 8) {
                        longlong2 f[8]; u64t sp[8];
                        #pragma unroll
                        for (int q = 0; q < 8; q++) {
                            int   s  = __shfl_sync(0xffffffffu, sid, kk + q);
                            float sc = __shfl_sync(0xffffffffu, sv, kk + q);
                            f[q] = feat2[s * 32 + lane];
                            sp[q] = pack2(sc, sc);
                        }
                        #pragma unroll
                        for (int q = 0; q < 8; q++) {
                            ffma2(acc0, sp[q], (u64t)f[q].x);
                            ffma2(acc1, sp[q], (u64t)f[q].y);
                        }
                    }
                    for (; kk < n; kk++) {
                        int   s  = __shfl_sync(0xffffffffu, sid, kk);
                        float sc = __shfl_sync(0xffffffffu, sv, kk);
                        longlong2 f = feat2[s * 32 + lane];
                        u64t sp = pack2(sc, sc);
                        ffma2(acc0, sp, (u64t)f.x);
                        ffma2(acc1, sp, (u64t)f.y);
                    }
                }
            }
            float2 a0 = unpack2(acc0), a1 = unpack2(acc1);
            ((float4*)myBuf)[i * 32 + lane] = make_float4(a0.x, a0.y, a1.x, a1.y);
        }
        __syncwarp();

        // ---- GEMM1 (FFMA2) ----
        u64t g00 = 0, g01 = 0, g10 = 0, g11 = 0, g20 = 0, g21 = 0, g30 = 0, g31 = 0;
        #pragma unroll 4
        for (int k = 0; k < F1; k++) {
            longlong2 wv = sW1ll[k * 32 + lane];
            float a0 = myBuf[0 * 128 + k], a1 = myBuf[1 * 128 + k];
            float a2 = myBuf[2 * 128 + k], a3 = myBuf[3 * 128 + k];
            u64t p0 = pack2(a0, a0), p1 = pack2(a1, a1);
            u64t p2 = pack2(a2, a2), p3 = pack2(a3, a3);
            ffma2(g00, p0, (u64t)wv.x); ffma2(g01, p0, (u64t)wv.y);
            ffma2(g10, p1, (u64t)wv.x); ffma2(g11, p1, (u64t)wv.y);
            ffma2(g20, p2, (u64t)wv.x); ffma2(g21, p2, (u64t)wv.y);
            ffma2(g30, p3, (u64t)wv.x); ffma2(g31, p3, (u64t)wv.y);
        }
        __syncwarp();

        // ---- epilogue1: v = relu(acc*s_in + b1) * s_out ----
        #pragma unroll
        for (int i = 0; i < 4; i++) {
            int r = r0 + i;
            float si = (r < NN) ? g_sin[r] : 1.0f;
            float so = (r < NN) ? g_sout[r] : 0.0f;
            float2 lo = unpack2(i == 0 ? g00 : i == 1 ? g10 : i == 2 ? g20 : g30);
            float2 hi = unpack2(i == 0 ? g01 : i == 1 ? g11 : i == 2 ? g21 : g31);
            float4 v;
            v.x = fmaxf(fmaf(lo.x, si, b1v.x), 0.f) * so;
            v.y = fmaxf(fmaf(lo.y, si, b1v.y), 0.f) * so;
            v.z = fmaxf(fmaf(hi.x, si, b1v.z), 0.f) * so;
            v.w = fmaxf(fmaf(hi.y, si, b1v.w), 0.f) * so;
            ((float4*)myBuf)[i * 32 + lane] = v;
        }
        __syncwarp();

        // ---- GEMM2 (FFMA2) ----
        u64t c0 = 0, c1 = 0, c2 = 0, c3 = 0;
        #pragma unroll 4
        for (int k = 0; k < F1; k++) {
            u64t wv = sW2ll[k * 32 + lane];
            float a0 = myBuf[0 * 128 + k], a1 = myBuf[1 * 128 + k];
            float a2 = myBuf[2 * 128 + k], a3 = myBuf[3 * 128 + k];
            ffma2(c0, pack2(a0, a0), wv);
            ffma2(c1, pack2(a1, a1), wv);
            ffma2(c2, pack2(a2, a2), wv);
            ffma2(c3, pack2(a3, a3), wv);
        }

        #pragma unroll
        for (int i = 0; i < 4; i++) {
            int r = r0 + i;
            if (r < NN) {
                float2 c = unpack2(i == 0 ? c0 : i == 1 ? c1 : i == 2 ? c2 : c3);
                ((float2*)g_h2)[r * 32 + lane] = c;
            }
        }
        __syncwarp();
    }
}

// ---------------- fused: gather2 + bias + log_softmax (+ zero deg for next run) ----------------
__global__ void k_layer2(float* __restrict__ out, const float* __restrict__ b2) {
    int t = blockIdx.x * blockDim.x + threadIdx.x;

    // tail duty: re-zero degree arrays for the next graph replay
    if (t < NN / 4) {
        ((int4*)g_degout)[t] = make_int4(0, 0, 0, 0);
        ((int4*)g_degin)[t]  = make_int4(0, 0, 0, 0);
    }

    int warp = t >> 5;
    int lane = threadIdx.x & 31;
    int g = lane >> 4;
    int sub = lane & 15;
    int r = warp * 2 + g;
    if (r >= NN) return;
    unsigned gmask = 0xFFFFu << (g * 16);

    int beg = __ldg(&g_rowstart[r]), end = __ldg(&g_rowstart[r + 1]);
    u64t acc0 = 0, acc1 = 0;
    const longlong2* h2v = (const longlong2*)g_h2;
    for (int j = beg; j < end; j += 16) {
        int n = min(16, end - j);
        int sid = (sub < n) ? g_csrc[j + sub] : 0;
        int kk = 0;
        for (; kk + 8 <= n; kk += 8) {
            longlong2 f[8];
            #pragma unroll
            for (int q = 0; q < 8; q++) {
                int s = __shfl_sync(gmask, sid, kk + q, 16);
                f[q] = h2v[s * 16 + sub];
            }
            #pragma unroll
            for (int q = 0; q < 8; q++) {
                fadd2(acc0, (u64t)f[q].x);
                fadd2(acc1, (u64t)f[q].y);
            }
        }
        for (; kk < n; kk++) {
            int s = __shfl_sync(gmask, sid, kk, 16);
            longlong2 f = h2v[s * 16 + sub];
            fadd2(acc0, (u64t)f.x);
            fadd2(acc1, (u64t)f.y);
        }
    }

    float si = g_sin[r];
    float2 a0 = unpack2(acc0), a1 = unpack2(acc1);
    float4 b = ((const float4*)b2)[sub];
    float y0 = fmaf(a0.x, si, b.x);
    float y1 = fmaf(a0.y, si, b.y);
    float y2 = fmaf(a1.x, si, b.z);
    float y3 = fmaf(a1.y, si, b.w);

    float m = fmaxf(fmaxf(y0, y1), fmaxf(y2, y3));
    #pragma unroll
    for (int off = 8; off > 0; off >>= 1)
        m = fmaxf(m, __shfl_xor_sync(gmask, m, off, 16));
    float ssum = expf(y0 - m) + expf(y1 - m) + expf(y2 - m) + expf(y3 - m);
    #pragma unroll
    for (int off = 8; off > 0; off >>= 1)
        ssum += __shfl_xor_sync(gmask, ssum, off, 16);
    float l = m + logf(ssum);

    ((float4*)out)[r * 16 + sub] = make_float4(y0 - l, y1 - l, y2 - l, y3 - l);
}

// ---------------- launch ----------------
extern "C" void kernel_launch(void* const* d_in, const int* in_sizes, int n_in,
                              void* d_out, int out_size) {
    const float* feat = (const float*)d_in[0];
    const int*   src  = (const int*)d_in[1];
    const int*   dst  = (const int*)d_in[2];
    const float* W1   = (const float*)d_in[3];
    const float* b1   = (const float*)d_in[4];
    const float* W2   = (const float*)d_in[5];
    const float* b2   = (const float*)d_in[6];
    float* out = (float*)d_out;

    (void)in_sizes; (void)n_in; (void)out_size;

    static bool attr_done = false;
    const int smem_bytes = (F1 * F1 + F1 * F2 + 8 * 4 * F1) * (int)sizeof(float); // 114688
    if (!attr_done) {
        cudaFuncSetAttribute(k_fused, cudaFuncAttributeMaxDynamicSharedMemorySize, smem_bytes);
        attr_done = true;
    }

    k_deg<<<(NE / 4 + 255) / 256, 256>>>((const int4*)src, (const int4*)dst);
    k_scan_all<<<1, SCAN_T>>>();
    k_fill<<<(NE / 4 + 255) / 256, 256>>>((const int4*)src, (const int4*)dst);
    k_fused<<<(NN + RPB - 1) / RPB, 256, smem_bytes>>>(
        feat, (const float4*)W1, (const float4*)W2, b1);
    k_layer2<<<(NN / 2 * 32 + 255) / 256, 256>>>(out, b2);
}

// round 14
// speedup vs baseline: 1.7807x; 1.7807x over previous
#include <cuda_runtime.h>

#define NN 50000
#define NE 800000
#define F1 128
#define F2 64
#define NB ((NN + 255) / 256)   // 196 scan blocks

typedef unsigned long long u64t;

// ---------------- packed f32x2 helpers ----------------
__device__ __forceinline__ u64t pack2(float a, float b) {
    u64t r; asm("mov.b64 %0,{%1,%2};" : "=l"(r) : "f"(a), "f"(b)); return r;
}
__device__ __forceinline__ float2 unpack2(u64t v) {
    float2 r; asm("mov.b64 {%0,%1},%2;" : "=f"(r.x), "=f"(r.y) : "l"(v)); return r;
}
__device__ __forceinline__ void ffma2(u64t& d, u64t a, u64t b) {
    asm("fma.rn.f32x2 %0,%1,%2,%0;" : "+l"(d) : "l"(a), "l"(b));
}
__device__ __forceinline__ void fadd2(u64t& d, u64t a) {
    asm("add.rn.f32x2 %0,%0,%1;" : "+l"(d) : "l"(a));
}

// ---------------- scratch ----------------
__device__ int   g_degout[NN];
__device__ int   g_degin[NN];
__device__ float g_sout[NN];
__device__ float g_sin[NN];
__device__ int   g_part[256];
__device__ int   g_rowstart[NN + 1];
__device__ int   g_cursor[NN];
__device__ int   g_csrc[NE];
__device__ float g_agg1[NN * F1];   // gathered layer-1 input
__device__ float g_h2[NN * F2];

// ---------------- degree ----------------
__global__ void k_zero_deg() {
    int i = blockIdx.x * blockDim.x + threadIdx.x;
    if (i < NN / 4) {
        ((int4*)g_degout)[i] = make_int4(0, 0, 0, 0);
        ((int4*)g_degin)[i]  = make_int4(0, 0, 0, 0);
    }
}

__global__ void k_deg(const int4* __restrict__ src4, const int4* __restrict__ dst4) {
    int i = blockIdx.x * blockDim.x + threadIdx.x;
    if (i < NE / 4) {
        int4 s = src4[i], d = dst4[i];
        atomicAdd(&g_degout[s.x], 1); atomicAdd(&g_degout[s.y], 1);
        atomicAdd(&g_degout[s.z], 1); atomicAdd(&g_degout[s.w], 1);
        atomicAdd(&g_degin[d.x], 1);  atomicAdd(&g_degin[d.y], 1);
        atomicAdd(&g_degin[d.z], 1);  atomicAdd(&g_degin[d.w], 1);
    }
}

// ---------------- scan (3 kernels, proven config) ----------------
__global__ void k_scan1() {
    __shared__ int sh[256];
    int i = blockIdx.x * 256 + threadIdx.x;
    int din = 0;
    if (i < NN) {
        din = g_degin[i];
        g_sout[i] = rsqrtf(fmaxf((float)g_degout[i], 1.0f));
        g_sin[i]  = rsqrtf(fmaxf((float)din, 1.0f));
    }
    sh[threadIdx.x] = din;
    __syncthreads();
    for (int s = 128; s > 0; s >>= 1) {
        if (threadIdx.x < s) sh[threadIdx.x] += sh[threadIdx.x + s];
        __syncthreads();
    }
    if (threadIdx.x == 0) g_part[blockIdx.x] = sh[0];
}

__global__ void k_scan2() {
    __shared__ int sh[256];
    int t = threadIdx.x;
    int v = (t < NB) ? g_part[t] : 0;
    sh[t] = v;
    __syncthreads();
    for (int off = 1; off < 256; off <<= 1) {
        int x = (t >= off) ? sh[t - off] : 0;
        __syncthreads();
        sh[t] += x;
        __syncthreads();
    }
    g_part[t] = sh[t] - v;
    if (t == 255) g_rowstart[NN] = sh[255];
}

__global__ void k_scan3() {
    __shared__ int sh[256];
    int t = threadIdx.x;
    int i = blockIdx.x * 256 + t;
    int v = (i < NN) ? g_degin[i] : 0;
    sh[t] = v;
    __syncthreads();
    for (int off = 1; off < 256; off <<= 1) {
        int x = (t >= off) ? sh[t - off] : 0;
        __syncthreads();
        sh[t] += x;
        __syncthreads();
    }
    if (i < NN) {
        g_rowstart[i] = g_part[blockIdx.x] + sh[t] - v;
        g_cursor[i] = 0;
    }
}

__global__ void k_fill(const int4* __restrict__ src4, const int4* __restrict__ dst4) {
    int i = blockIdx.x * blockDim.x + threadIdx.x;
    if (i < NE / 4) {
        int4 s = src4[i], d = dst4[i];
        int p;
        p = atomicAdd(&g_cursor[d.x], 1); g_csrc[g_rowstart[d.x] + p] = s.x;
        p = atomicAdd(&g_cursor[d.y], 1); g_csrc[g_rowstart[d.y] + p] = s.y;
        p = atomicAdd(&g_cursor[d.z], 1); g_csrc[g_rowstart[d.z] + p] = s.z;
        p = atomicAdd(&g_cursor[d.w], 1); g_csrc[g_rowstart[d.w] + p] = s.w;
    }
}

// ---------------- gather1: one warp per node, NO smem, high occupancy ----------------
__global__ __launch_bounds__(256)
void k_gather(const float* __restrict__ featp) {
    int warp = (blockIdx.x * blockDim.x + threadIdx.x) >> 5;
    int lane = threadIdx.x & 31;
    if (warp >= NN) return;
    int r = warp;

    const longlong2* feat2 = (const longlong2*)featp;
    u64t acc0 = 0, acc1 = 0;
    int beg = __ldg(&g_rowstart[r]), end = __ldg(&g_rowstart[r + 1]);
    for (int j = beg; j < end; j += 32) {
        int n = min(32, end - j);
        int sid = 0; float sv = 0.f;
        if (lane < n) { sid = g_csrc[j + lane]; sv = g_sout[sid]; }
        int kk = 0;
        for (; kk + 8 <= n; kk += 8) {
            longlong2 f[8]; u64t sp[8];
            #pragma unroll
            for (int q = 0; q < 8; q++) {
                int   s  = __shfl_sync(0xffffffffu, sid, kk + q);
                float sc = __shfl_sync(0xffffffffu, sv, kk + q);
                f[q] = feat2[s * 32 + lane];
                sp[q] = pack2(sc, sc);
            }
            #pragma unroll
            for (int q = 0; q < 8; q++) {
                ffma2(acc0, sp[q], (u64t)f[q].x);
                ffma2(acc1, sp[q], (u64t)f[q].y);
            }
        }
        for (; kk < n; kk++) {
            int   s  = __shfl_sync(0xffffffffu, sid, kk);
            float sc = __shfl_sync(0xffffffffu, sv, kk);
            longlong2 f = feat2[s * 32 + lane];
            u64t sp = pack2(sc, sc);
            ffma2(acc0, sp, (u64t)f.x);
            ffma2(acc1, sp, (u64t)f.y);
        }
    }
    float2 a0 = unpack2(acc0), a1 = unpack2(acc1);
    ((float4*)g_agg1)[r * 32 + lane] = make_float4(a0.x, a0.y, a1.x, a1.y);
}

// ---------------- double GEMM: streams g_agg1, smem weights, fma-bound ----------------
#define RPB 64  // 8 warps * 4 rows * 2 passes

__global__ __launch_bounds__(256, 2)
void k_gemm(const float4* __restrict__ W1g, const float4* __restrict__ W2g,
            const float* __restrict__ b1g) {
    extern __shared__ float sm[];
    float* sW1 = sm;                       // 16384 floats
    float* sW2 = sm + F1 * F1;             // 8192 floats
    float* sBuf = sW2 + F1 * F2;           // 8 warps * 512 floats

    int tid = threadIdx.x;
    #pragma unroll 4
    for (int i = tid; i < (F1 * F1) / 4; i += 256) ((float4*)sW1)[i] = W1g[i];
    #pragma unroll 2
    for (int i = tid; i < (F1 * F2) / 4; i += 256) ((float4*)sW2)[i] = W2g[i];
    __syncthreads();

    int w = tid >> 5, lane = tid & 31;
    float* myBuf = sBuf + w * 512;
    float4 b1v = ((const float4*)b1g)[lane];
    const longlong2* sW1ll = (const longlong2*)sW1;
    const u64t*      sW2ll = (const u64t*)sW2;

    for (int pass = 0; pass < 2; pass++) {
        int r0 = blockIdx.x * RPB + pass * 32 + w * 4;

        // stream 4 agg rows (sequential, prefetch-friendly)
        #pragma unroll
        for (int i = 0; i < 4; i++) {
            int r = r0 + i;
            float4 a = (r < NN) ? __ldg(&((const float4*)g_agg1)[r * 32 + lane])
                                : make_float4(0.f, 0.f, 0.f, 0.f);
            ((float4*)myBuf)[i * 32 + lane] = a;
        }
        __syncwarp();

        // ---- GEMM1 (FFMA2) ----
        u64t g00 = 0, g01 = 0, g10 = 0, g11 = 0, g20 = 0, g21 = 0, g30 = 0, g31 = 0;
        #pragma unroll 4
        for (int k = 0; k < F1; k++) {
            longlong2 wv = sW1ll[k * 32 + lane];
            float a0 = myBuf[0 * 128 + k], a1 = myBuf[1 * 128 + k];
            float a2 = myBuf[2 * 128 + k], a3 = myBuf[3 * 128 + k];
            u64t p0 = pack2(a0, a0), p1 = pack2(a1, a1);
            u64t p2 = pack2(a2, a2), p3 = pack2(a3, a3);
            ffma2(g00, p0, (u64t)wv.x); ffma2(g01, p0, (u64t)wv.y);
            ffma2(g10, p1, (u64t)wv.x); ffma2(g11, p1, (u64t)wv.y);
            ffma2(g20, p2, (u64t)wv.x); ffma2(g21, p2, (u64t)wv.y);
            ffma2(g30, p3, (u64t)wv.x); ffma2(g31, p3, (u64t)wv.y);
        }
        __syncwarp();

        // ---- epilogue1: v = relu(acc*s_in + b1) * s_out ----
        #pragma unroll
        for (int i = 0; i < 4; i++) {
            int r = r0 + i;
            float si = (r < NN) ? g_sin[r] : 1.0f;
            float so = (r < NN) ? g_sout[r] : 0.0f;
            float2 lo = unpack2(i == 0 ? g00 : i == 1 ? g10 : i == 2 ? g20 : g30);
            float2 hi = unpack2(i == 0 ? g01 : i == 1 ? g11 : i == 2 ? g21 : g31);
            float4 v;
            v.x = fmaxf(fmaf(lo.x, si, b1v.x), 0.f) * so;
            v.y = fmaxf(fmaf(lo.y, si, b1v.y), 0.f) * so;
            v.z = fmaxf(fmaf(hi.x, si, b1v.z), 0.f) * so;
            v.w = fmaxf(fmaf(hi.y, si, b1v.w), 0.f) * so;
            ((float4*)myBuf)[i * 32 + lane] = v;
        }
        __syncwarp();

        // ---- GEMM2 (FFMA2) ----
        u64t c0 = 0, c1 = 0, c2 = 0, c3 = 0;
        #pragma unroll 4
        for (int k = 0; k < F1; k++) {
            u64t wv = sW2ll[k * 32 + lane];
            float a0 = myBuf[0 * 128 + k], a1 = myBuf[1 * 128 + k];
            float a2 = myBuf[2 * 128 + k], a3 = myBuf[3 * 128 + k];
            ffma2(c0, pack2(a0, a0), wv);
            ffma2(c1, pack2(a1, a1), wv);
            ffma2(c2, pack2(a2, a2), wv);
            ffma2(c3, pack2(a3, a3), wv);
        }

        #pragma unroll
        for (int i = 0; i < 4; i++) {
            int r = r0 + i;
            if (r < NN) {
                float2 c = unpack2(i == 0 ? c0 : i == 1 ? c1 : i == 2 ? c2 : c3);
                ((float2*)g_h2)[r * 32 + lane] = c;
            }
        }
        __syncwarp();
    }
}

// ---------------- fused: gather2 + bias + log_softmax (R10-proven 4-deep) ----------------
__global__ void k_layer2(float* __restrict__ out, const float* __restrict__ b2) {
    int t = blockIdx.x * blockDim.x + threadIdx.x;
    int warp = t >> 5;
    int lane = threadIdx.x & 31;
    int g = lane >> 4;
    int sub = lane & 15;
    int r = warp * 2 + g;
    if (r >= NN) return;
    unsigned gmask = 0xFFFFu << (g * 16);

    int beg = __ldg(&g_rowstart[r]), end = __ldg(&g_rowstart[r + 1]);
    u64t acc0 = 0, acc1 = 0;
    const longlong2* h2v = (const longlong2*)g_h2;
    for (int j = beg; j < end; j += 16) {
        int n = min(16, end - j);
        int sid = (sub < n) ? g_csrc[j + sub] : 0;
        int kk = 0;
        for (; kk + 4 <= n; kk += 4) {
            longlong2 f[4];
            #pragma unroll
            for (int q = 0; q < 4; q++) {
                int s = __shfl_sync(gmask, sid, kk + q, 16);
                f[q] = h2v[s * 16 + sub];
            }
            #pragma unroll
            for (int q = 0; q < 4; q++) {
                fadd2(acc0, (u64t)f[q].x);
                fadd2(acc1, (u64t)f[q].y);
            }
        }
        for (; kk < n; kk++) {
            int s = __shfl_sync(gmask, sid, kk, 16);
            longlong2 f = h2v[s * 16 + sub];
            fadd2(acc0, (u64t)f.x);
            fadd2(acc1, (u64t)f.y);
        }
    }

    float si = g_sin[r];
    float2 a0 = unpack2(acc0), a1 = unpack2(acc1);
    float4 b = ((const float4*)b2)[sub];
    float y0 = fmaf(a0.x, si, b.x);
    float y1 = fmaf(a0.y, si, b.y);
    float y2 = fmaf(a1.x, si, b.z);
    float y3 = fmaf(a1.y, si, b.w);

    float m = fmaxf(fmaxf(y0, y1), fmaxf(y2, y3));
    #pragma unroll
    for (int off = 8; off > 0; off >>= 1)
        m = fmaxf(m, __shfl_xor_sync(gmask, m, off, 16));
    float ssum = expf(y0 - m) + expf(y1 - m) + expf(y2 - m) + expf(y3 - m);
    #pragma unroll
    for (int off = 8; off > 0; off >>= 1)
        ssum += __shfl_xor_sync(gmask, ssum, off, 16);
    float l = m + logf(ssum);

    ((float4*)out)[r * 16 + sub] = make_float4(y0 - l, y1 - l, y2 - l, y3 - l);
}

// ---------------- launch ----------------
extern "C" void kernel_launch(void* const* d_in, const int* in_sizes, int n_in,
                              void* d_out, int out_size) {
    const float* feat = (const float*)d_in[0];
    const int*   src  = (const int*)d_in[1];
    const int*   dst  = (const int*)d_in[2];
    const float* W1   = (const float*)d_in[3];
    const float* b1   = (const float*)d_in[4];
    const float* W2   = (const float*)d_in[5];
    const float* b2   = (const float*)d_in[6];
    float* out = (float*)d_out;

    (void)in_sizes; (void)n_in; (void)out_size;

    static bool attr_done = false;
    const int smem_bytes = (F1 * F1 + F1 * F2 + 8 * 4 * F1) * (int)sizeof(float); // 114688
    if (!attr_done) {
        cudaFuncSetAttribute(k_gemm, cudaFuncAttributeMaxDynamicSharedMemorySize, smem_bytes);
        attr_done = true;
    }

    k_zero_deg<<<(NN / 4 + 255) / 256, 256>>>();
    k_deg<<<(NE / 4 + 255) / 256, 256>>>((const int4*)src, (const int4*)dst);
    k_scan1<<<NB, 256>>>();
    k_scan2<<<1, 256>>>();
    k_scan3<<<NB, 256>>>();
    k_fill<<<(NE / 4 + 255) / 256, 256>>>((const int4*)src, (const int4*)dst);
    k_gather<<<(NN * 32 + 255) / 256, 256>>>(feat);
    k_gemm<<<(NN + RPB - 1) / RPB, 256, smem_bytes>>>(
        (const float4*)W1, (const float4*)W2, b1);
    k_layer2<<<(NN / 2 * 32 + 255) / 256, 256>>>(out, b2);
}